// round 6
// baseline (speedup 1.0000x reference)
#include <cuda_runtime.h>
#include <cstdint>

// Problem: input [B=128, C=2, H=512, W=512] fp32.
// out[:,0] = inclusive cumsum along x (contiguous axis)
// out[:,1] = inclusive cumsum along y (stride-W axis)
//
// One fused kernel. Grid = 64 y-role blocks (FIRST, long-lived, float4-per-
// thread column scan) + 8192 x-role blocks (warp-per-row float4 scan).
// Front-loading the y-blocks starts them at t=0 on distinct SMs so their
// serial column walks overlap the whole x stream; no latency-bound tail.

#define Bn 128
#define Wn 512
#define Y_BLOCKS 64
#define X_BLOCKS 8192            // 65536 rows / 8 warps per block
#define GRID_BLOCKS (Y_BLOCKS + X_BLOCKS)

// ---------------------------------------------------------------------------
// x-role: one warp per row of channel 0. 4 iterations of float4-per-lane.
// ---------------------------------------------------------------------------
__device__ __forceinline__ void do_scan_x(const float* __restrict__ in,
                                          float* __restrict__ out,
                                          unsigned xbid) {
    const unsigned gwarp = xbid * 8u + (threadIdx.x >> 5);   // 0..65535
    const unsigned lane  = threadIdx.x & 31u;

    const unsigned b = gwarp >> 9;     // / 512
    const unsigned y = gwarp & 511u;   // % 512

    const size_t base = ((size_t)(b * 2u + 0u) * Wn + y) * Wn;  // channel 0
    const float4* __restrict__ in4  = (const float4*)(in + base);
    float4* __restrict__       out4 = (float4*)(out + base);

    float carry = 0.0f;
#pragma unroll
    for (int it = 0; it < 4; ++it) {
        float4 v = in4[it * 32 + lane];

        float s0 = v.x;
        float s1 = s0 + v.y;
        float s2 = s1 + v.z;
        float s3 = s2 + v.w;

        float incl = s3;
#pragma unroll
        for (int off = 1; off < 32; off <<= 1) {
            float n = __shfl_up_sync(0xffffffffu, incl, off);
            if (lane >= (unsigned)off) incl += n;
        }
        float excl = incl - s3 + carry;

        float4 o;
        o.x = s0 + excl;
        o.y = s1 + excl;
        o.z = s2 + excl;
        o.w = s3 + excl;
        out4[it * 32 + lane] = o;

        carry += __shfl_sync(0xffffffffu, incl, 31);
    }
}

// ---------------------------------------------------------------------------
// y-role: one thread per 4 adjacent columns (float4), 4 independent
// accumulators, serial walk down 512 rows, unrolled by 8 (4KB/warp in
// flight). 128 threads per image -> 2 images per 256-thread block,
// 64 blocks total. Every warp row-step is a contiguous 512B transaction.
// ---------------------------------------------------------------------------
__device__ __forceinline__ void do_scan_y(const float* __restrict__ in,
                                          float* __restrict__ out,
                                          unsigned ybid) {
    const unsigned t  = ybid * 256u + threadIdx.x;   // 0..16383
    const unsigned b  = t >> 7;                      // image (128 threads/image)
    const unsigned xq = t & 127u;                    // float4 column group

    const size_t base = ((size_t)(b * 2u + 1u) * Wn) * Wn + xq * 4u;  // ch 1
    const float4* __restrict__ ip4 = (const float4*)(in + base);
    float4* __restrict__       op4 = (float4*)(out + base);

    float4 acc = make_float4(0.f, 0.f, 0.f, 0.f);
#pragma unroll 1
    for (int y0 = 0; y0 < Wn; y0 += 8) {
        float4 v[8];
#pragma unroll
        for (int k = 0; k < 8; ++k)
            v[k] = ip4[(size_t)(y0 + k) * (Wn / 4)];
#pragma unroll
        for (int k = 0; k < 8; ++k) {
            acc.x += v[k].x;
            acc.y += v[k].y;
            acc.z += v[k].z;
            acc.w += v[k].w;
            op4[(size_t)(y0 + k) * (Wn / 4)] = acc;
        }
    }
}

__global__ void __launch_bounds__(256) fused_scan_kernel(const float* __restrict__ in,
                                                         float* __restrict__ out) {
    const unsigned bid = blockIdx.x;
    if (bid < Y_BLOCKS) {
        do_scan_y(in, out, bid);              // long-lived, starts at t=0
    } else {
        do_scan_x(in, out, bid - Y_BLOCKS);   // short streaming blocks backfill
    }
}

extern "C" void kernel_launch(void* const* d_in, const int* in_sizes, int n_in,
                              void* d_out, int out_size) {
    const float* in = (const float*)d_in[0];
    float* out = (float*)d_out;
    fused_scan_kernel<<<GRID_BLOCKS, 256>>>(in, out);
}

// round 10
// speedup vs baseline: 1.3528x; 1.3528x over previous
#include <cuda_runtime.h>
#include <cstdint>

// Problem: input [B=128, C=2, H=512, W=512] fp32.
// out[:,0] = inclusive cumsum along x (contiguous axis)
// out[:,1] = inclusive cumsum along y (stride-W axis)
//
// One fused kernel, all blocks short-lived and bandwidth-bound:
//  x-role (8192 blocks): one warp per row, float4 warp-scan.
//  y-role (4096 blocks): 512x16 tile staged through 32KB smem.
//    load tile (coalesced float4, high MLP) -> segmented scan in smem
//    (16 segments x 32 rows) -> spine prefix -> coalesced float4 store.
// Interleaved bid%3==0 -> y so both traffic types share every wave.

#define Bn 128
#define Wn 512
#define TCOLS 16                    // tile width (columns)
#define TSEG 32                     // rows per scan segment
#define NSEG 16                     // 512 / 32
#define Y_BLOCKS 4096               // 128 images * (512/16) col-tiles
#define X_BLOCKS 8192               // 65536 rows / 8 warps
#define GRID_BLOCKS (Y_BLOCKS + X_BLOCKS)

// ---------------------------------------------------------------------------
// x-role: one warp per row of channel 0.
// ---------------------------------------------------------------------------
__device__ __forceinline__ void do_scan_x(const float* __restrict__ in,
                                          float* __restrict__ out,
                                          unsigned xbid) {
    const unsigned gwarp = xbid * 8u + (threadIdx.x >> 5);   // 0..65535
    const unsigned lane  = threadIdx.x & 31u;

    const unsigned b = gwarp >> 9;
    const unsigned y = gwarp & 511u;

    const size_t base = ((size_t)(b * 2u + 0u) * Wn + y) * Wn;  // channel 0
    const float4* __restrict__ in4  = (const float4*)(in + base);
    float4* __restrict__       out4 = (float4*)(out + base);

    float carry = 0.0f;
#pragma unroll
    for (int it = 0; it < 4; ++it) {
        float4 v = in4[it * 32 + lane];

        float s0 = v.x;
        float s1 = s0 + v.y;
        float s2 = s1 + v.z;
        float s3 = s2 + v.w;

        float incl = s3;
#pragma unroll
        for (int off = 1; off < 32; off <<= 1) {
            float n = __shfl_up_sync(0xffffffffu, incl, off);
            if (lane >= (unsigned)off) incl += n;
        }
        float excl = incl - s3 + carry;

        float4 o;
        o.x = s0 + excl;
        o.y = s1 + excl;
        o.z = s2 + excl;
        o.w = s3 + excl;
        out4[it * 32 + lane] = o;

        carry += __shfl_sync(0xffffffffu, incl, 31);
    }
}

// ---------------------------------------------------------------------------
// y-role: 512x16 tile of channel 1 through smem. Load and store phases use
// the identical float4-coalesced mapping (512B per warp-instruction).
// ---------------------------------------------------------------------------
__device__ __forceinline__ void do_scan_y(const float* __restrict__ in,
                                          float* __restrict__ out,
                                          unsigned ybid,
                                          float* __restrict__ tile,
                                          float* __restrict__ spine,
                                          float* __restrict__ pre) {
    const unsigned tid = threadIdx.x;
    const unsigned b   = ybid >> 5;          // image (32 col-tiles per image)
    const unsigned tc  = ybid & 31u;         // col-tile
    const unsigned col0 = tc * TCOLS;

    const size_t base = ((size_t)(b * 2u + 1u) * Wn) * Wn + col0;  // ch1 row0

    const unsigned quad = tid & 3u;          // float4 within 16-col tile row
    const unsigned r0   = tid >> 2;          // 0..63

    // ---- load: 2048 float4s, 8 per thread, coalesced, independent ----
    {
        const float4* __restrict__ in4 = (const float4*)(in + base);
        float4* __restrict__ tile4 = (float4*)tile;
#pragma unroll
        for (int batch = 0; batch < 8; ++batch) {
            const unsigned row = batch * 64u + r0;
            tile4[row * 4u + quad] = in4[(size_t)row * 128u + quad];
        }
    }
    __syncthreads();

    // ---- scan: thread (c, s) scans rows [s*32, s*32+32) of column c ----
    const unsigned c = tid & 15u;
    const unsigned s = tid >> 4;
    {
        float acc = 0.0f;
#pragma unroll
        for (int i = 0; i < TSEG; ++i) {
            const unsigned idx = (s * TSEG + i) * TCOLS + c;
            acc += tile[idx];
            tile[idx] = acc;               // in-place inclusive prefix
        }
        spine[s * TCOLS + c] = acc;        // segment total
    }
    __syncthreads();

    // ---- spine prefix: pre[s][c] = sum of spine[s2][c], s2 < s ----
    {
        float off = 0.0f;
        for (unsigned s2 = 0; s2 < s; ++s2)
            off += spine[s2 * TCOLS + c];
        pre[s * TCOLS + c] = off;
    }
    __syncthreads();

    // ---- store: same float4 mapping as load (fully coalesced) ----
    {
        float4* __restrict__ out4 = (float4*)(out + base);
        const float4* __restrict__ tile4 = (const float4*)tile;
        const float* __restrict__ prow = pre + quad * 4u;   // 4 col offsets
#pragma unroll
        for (int batch = 0; batch < 8; ++batch) {
            const unsigned row = batch * 64u + r0;
            const unsigned seg = row >> 5;                  // row / TSEG
            float4 v = tile4[row * 4u + quad];
            v.x += prow[seg * TCOLS + 0];
            v.y += prow[seg * TCOLS + 1];
            v.z += prow[seg * TCOLS + 2];
            v.w += prow[seg * TCOLS + 3];
            out4[(size_t)row * 128u + quad] = v;
        }
    }
}

__global__ void __launch_bounds__(256) fused_scan_kernel(const float* __restrict__ in,
                                                         float* __restrict__ out) {
    __shared__ float tile[TCOLS * Wn];       // 32 KB
    __shared__ float spine[NSEG * TCOLS];    // 1 KB
    __shared__ float pre[NSEG * TCOLS];      // 1 KB

    const unsigned bid = blockIdx.x;
    const unsigned q = bid / 3u;
    if (bid == q * 3u) {
        do_scan_y(in, out, q, tile, spine, pre);     // 4096 y-tiles
    } else {
        do_scan_x(in, out, bid - q - 1u);            // 8192 x-blocks
    }
}

extern "C" void kernel_launch(void* const* d_in, const int* in_sizes, int n_in,
                              void* d_out, int out_size) {
    const float* in = (const float*)d_in[0];
    float* out = (float*)d_out;
    fused_scan_kernel<<<GRID_BLOCKS, 256>>>(in, out);
}